// round 17
// baseline (speedup 1.0000x reference)
#include <cuda_runtime.h>
#include <cuda_bf16.h>
#include <cuda_fp16.h>

// GIN MessagePassing — round 15.
// K1: fp16 hi/lo 2-pass, warp tile 32x64, BM=128 BN=256, split-K=4.
// K2/K3: fp16 hi/lo 2-pass (A hi/lo x W fp16), warp tile 32x32, BM=BN=128.
// K2 fuses reduce ((1+eps)x + sum of 4 partials) into its A-loader.

#define BM 128
#define BK 32
#define STRD 80
#define PL (128 * STRD)              // 128-row plane = 10240 B

// K1: planes Ahi(128), Alo(128), B(256 rows)
#define F_OFF_ALO (PL)
#define F_OFF_B   (2 * PL)
#define F_STAGE   (2 * PL + 256 * STRD)   // 40960
#define F_SMEM    (2 * F_STAGE)           // 81920

// K2/K3: planes Ahi, Alo, B (128 rows each)
#define H_OFF_ALO (PL)
#define H_OFF_B   (2 * PL)
#define H_STAGE   (3 * PL)           // 30720
#define H_SMEM    (2 * H_STAGE)      // 61440

#define PSTR (8LL * 4096 * 256)

// ---------------- scratch ----------------
__device__ float g_h1[8u * 4096u * 512u];
__device__ float g_part[4u * 8u * 4096u * 256u];
__device__ __align__(16) __half g_Bx_h[8u * 256u * 4096u];
__device__ __align__(16) __half g_W1_h[512u * 256u];
__device__ __align__(16) __half g_W2_h[256u * 512u];

__device__ __forceinline__ unsigned s2u(const void* p) {
    unsigned a;
    asm("{ .reg .u64 t; cvta.to.shared.u64 t, %1; cvt.u32.u64 %0, t; }"
        : "=r"(a) : "l"(p));
    return a;
}
__device__ __forceinline__ void ldsm4(unsigned r[4], unsigned a) {
    asm volatile("ldmatrix.sync.aligned.m8n8.x4.shared.b16 {%0,%1,%2,%3}, [%4];"
                 : "=r"(r[0]), "=r"(r[1]), "=r"(r[2]), "=r"(r[3]) : "r"(a));
}
__device__ __forceinline__ void mma_h(float c[4], const unsigned a[4],
                                      const unsigned b[2]) {
    asm volatile(
        "mma.sync.aligned.m16n8k16.row.col.f32.f16.f16.f32 "
        "{%0,%1,%2,%3},{%4,%5,%6,%7},{%8,%9},{%0,%1,%2,%3};"
        : "+f"(c[0]), "+f"(c[1]), "+f"(c[2]), "+f"(c[3])
        : "r"(a[0]), "r"(a[1]), "r"(a[2]), "r"(a[3]), "r"(b[0]), "r"(b[1]));
}
__device__ __forceinline__ void cpa16(unsigned dst, const void* src) {
    asm volatile("cp.async.ca.shared.global [%0], [%1], 16;"
                 :: "r"(dst), "l"(src) : "memory");
}
__device__ __forceinline__ unsigned pack2h(float x, float y) {
    const __half hx = __float2half(x), hy = __float2half(y);
    return (unsigned)__half_as_ushort(hx) |
           ((unsigned)__half_as_ushort(hy) << 16);
}

// ---------------- pack x: [B][4096][256] fp32 -> [B][256][4096] fp16 ----------------
__global__ __launch_bounds__(256)
void pack_x_h(const float* __restrict__ in, __half* __restrict__ o)
{
    __shared__ float t[32][33];
    const int b = blockIdx.z, K = 4096, N = 256;
    const float* ib = in + (long long)b * K * N;
    const int k0 = blockIdx.x * 32, n0 = blockIdx.y * 32;
    const int tx = threadIdx.x, ty = threadIdx.y;
#pragma unroll
    for (int i = 0; i < 4; ++i)
        t[ty + i * 8][tx] = ib[(long long)(k0 + ty + i * 8) * N + n0 + tx];
    __syncthreads();
    __half* ob = o + (long long)b * K * N;
#pragma unroll
    for (int i = 0; i < 4; ++i)
        ob[(long long)(n0 + ty + i * 8) * K + k0 + tx] =
            __float2half(t[tx][ty + i * 8]);
}

// ---------------- pack W: [K][N] fp32 -> [N][K] fp16 ----------------
__global__ __launch_bounds__(256)
void pack_w_h(const float* __restrict__ in, __half* __restrict__ o, int K, int N)
{
    __shared__ float t[32][33];
    const int k0 = blockIdx.x * 32, n0 = blockIdx.y * 32;
    const int tx = threadIdx.x, ty = threadIdx.y;
#pragma unroll
    for (int i = 0; i < 4; ++i)
        t[ty + i * 8][tx] = in[(long long)(k0 + ty + i * 8) * N + n0 + tx];
    __syncthreads();
#pragma unroll
    for (int i = 0; i < 4; ++i)
        o[(long long)(n0 + ty + i * 8) * K + k0 + tx] =
            __float2half(t[tx][ty + i * 8]);
}

// ================= K1: fp16 2-pass, warp tile 32x64, BN=256 =================
__global__ __launch_bounds__(512, 1)
void gemm_k1(const float* __restrict__ A, const __half* __restrict__ Bx,
             float* __restrict__ C, int lda, int ldC, int kseg,
             long long sA, long long sB, long long sC)
{
    extern __shared__ char smem[];
    const int tid  = threadIdx.x;
    const int wid  = tid >> 5;
    const int lane = tid & 31;
    const int wm   = wid & 3;        // 4 warps M x 32
    const int wn   = wid >> 2;       // 4 warps N x 64

    const int zz  = blockIdx.z;
    const int bz  = zz >> 2;
    const int sp  = zz & 3;
    const int k0s = sp * kseg;
    const long long row0 = (long long)blockIdx.y * BM;

    const float* Ap = A + (long long)bz * sA + row0 * lda;
    const __half* Bp = Bx + (long long)bz * sB;

    const unsigned sbase = s2u(smem);

    // A: 128 rows x 32 fp32; thread -> row tid>>2, 8-col group (tid&3)*8
    const int ar  = tid >> 2;
    const int ac0 = (tid & 3) * 8;
    float4 pa[2];
    auto ldA = [&](int k0) {
        const float* p = Ap + (long long)ar * lda + k0 + ac0;
        pa[0] = *(const float4*)(p);
        pa[1] = *(const float4*)(p + 4);
    };
    auto stA = [&](int s) {
        const float f[8] = {pa[0].x, pa[0].y, pa[0].z, pa[0].w,
                            pa[1].x, pa[1].y, pa[1].z, pa[1].w};
        unsigned hi[4], lo[4];
#pragma unroll
        for (int q = 0; q < 4; ++q) {
            const float a = f[2 * q], b = f[2 * q + 1];
            const float ra = a - __half2float(__float2half(a));
            const float rb = b - __half2float(__float2half(b));
            hi[q] = pack2h(a, b);
            lo[q] = pack2h(ra, rb);
        }
        char* base = smem + s * F_STAGE;
        const unsigned off = (unsigned)(ar * STRD + ac0 * 2);
        *(uint4*)(base + off)             = make_uint4(hi[0], hi[1], hi[2], hi[3]);
        *(uint4*)(base + F_OFF_ALO + off) = make_uint4(lo[0], lo[1], lo[2], lo[3]);
    };
    // B: 256 rows x 32 fp16; thread -> row tid>>1, 32B half (tid&1)
    const int br = tid >> 1;
    const int bc = (tid & 1) * 32;
    auto cpB = [&](int s, int k0) {
        const unsigned d = sbase + s * F_STAGE + F_OFF_B + br * STRD + bc;
        const __half* sp_ = Bp + (long long)br * lda + k0 + (bc >> 1);
        cpa16(d,      sp_);
        cpa16(d + 16, sp_ + 8);
        asm volatile("cp.async.commit_group;" ::: "memory");
    };

    ldA(k0s);
    cpB(0, k0s);
    stA(0);
    asm volatile("cp.async.wait_group 0;" ::: "memory");
    __syncthreads();

    float acc[2][8][4];
#pragma unroll
    for (int i = 0; i < 2; ++i)
#pragma unroll
        for (int j = 0; j < 8; ++j)
#pragma unroll
            for (int e = 0; e < 4; ++e) acc[i][j][e] = 0.f;

    const int lrow = lane & 7, quad = lane >> 3;
    const unsigned aoff =
        (unsigned)((wm * 32 + lrow + (quad & 1) * 8) * STRD + ((quad >> 1) * 8) * 2);
    const unsigned boff =
        (unsigned)((wn * 64 + lrow + (quad >> 1) * 8) * STRD + ((quad & 1) * 8) * 2);

    const int nIter = kseg >> 5;
    for (int it = 0; it < nIter; ++it) {
        const int s = it & 1;
        const unsigned sb = sbase + s * F_STAGE;
        const bool more = (it + 1 < nIter);
        if (more) { ldA(k0s + (it + 1) * BK); cpB(s ^ 1, k0s + (it + 1) * BK); }

#pragma unroll
        for (int k2 = 0; k2 < 2; ++k2) {
            const unsigned kb = (unsigned)(k2 * 32);
            unsigned a_hi[2][4], a_lo[2][4];
#pragma unroll
            for (int i = 0; i < 2; ++i) {
                ldsm4(a_hi[i], sb + aoff + i * 16 * STRD + kb);
                ldsm4(a_lo[i], sb + F_OFF_ALO + aoff + i * 16 * STRD + kb);
            }
#pragma unroll
            for (int p = 0; p < 4; ++p) {
                unsigned bfr[4];
                ldsm4(bfr, sb + F_OFF_B + boff + p * 16 * STRD + kb);
#pragma unroll
                for (int i = 0; i < 2; ++i) {
                    mma_h(acc[i][2 * p + 0], a_hi[i], bfr + 0);
                    mma_h(acc[i][2 * p + 1], a_hi[i], bfr + 2);
                    mma_h(acc[i][2 * p + 0], a_lo[i], bfr + 0);
                    mma_h(acc[i][2 * p + 1], a_lo[i], bfr + 2);
                }
            }
        }
        if (more) {
            stA(s ^ 1);
            asm volatile("cp.async.wait_group 0;" ::: "memory");
        }
        __syncthreads();
    }

    const int r4 = lane >> 2, c2 = (lane & 3) * 2;
    float* Cb = C + (long long)(sp * 8 + bz) * sC;
#pragma unroll
    for (int i = 0; i < 2; ++i) {
        const long long rg0 = row0 + wm * 32 + i * 16 + r4;
#pragma unroll
        for (int j = 0; j < 8; ++j) {
            const int cg = wn * 64 + j * 8 + c2;
            *(float2*)(Cb + rg0 * ldC + cg) =
                make_float2(acc[i][j][0], acc[i][j][1]);
            *(float2*)(Cb + (rg0 + 8) * ldC + cg) =
                make_float2(acc[i][j][2], acc[i][j][3]);
        }
    }
}

// ================= K2/K3: fp16 2-pass, warp tile 32x32 =================
template<int EPI>   // 2: compose + bias+relu    3: bias
__global__ __launch_bounds__(512, 1)
void gemm_h2(const float* __restrict__ A,
             const __half* __restrict__ W,
             float* __restrict__ C,
             const float* __restrict__ bias,
             const float* __restrict__ part,
             const float* __restrict__ epsp,
             int lda, int ldC, int kseg)
{
    extern __shared__ char smem[];
    const int tid  = threadIdx.x;
    const int wid  = tid >> 5;
    const int lane = tid & 31;
    const int wm   = wid & 3;
    const int wn   = wid >> 2;

    const int n0  = blockIdx.x * 128;
    const long long row0 = (long long)blockIdx.y * BM;

    const float* Ap = A + row0 * lda;
    const float* Pp = (EPI == 2) ? (part + row0 * lda) : nullptr;
    const __half* Bp = W + (long long)n0 * lda;

    float ev = 0.f;
    if (EPI == 2) ev = 1.0f + epsp[0];

    const unsigned sbase = s2u(smem);

    const int ar  = tid >> 2;
    const int ac0 = (tid & 3) * 8;
    float4 pa[2];
    auto ldA = [&](int k0) {
        const long long o = (long long)ar * lda + k0 + ac0;
        pa[0] = *(const float4*)(Ap + o);
        pa[1] = *(const float4*)(Ap + o + 4);
        if (EPI == 2) {
            pa[0].x *= ev; pa[0].y *= ev; pa[0].z *= ev; pa[0].w *= ev;
            pa[1].x *= ev; pa[1].y *= ev; pa[1].z *= ev; pa[1].w *= ev;
#pragma unroll
            for (int s = 0; s < 4; ++s) {
                const float4 q0 = *(const float4*)(Pp + s * PSTR + o);
                const float4 q1 = *(const float4*)(Pp + s * PSTR + o + 4);
                pa[0].x += q0.x; pa[0].y += q0.y; pa[0].z += q0.z; pa[0].w += q0.w;
                pa[1].x += q1.x; pa[1].y += q1.y; pa[1].z += q1.z; pa[1].w += q1.w;
            }
        }
    };
    auto stA = [&](int s) {
        const float f[8] = {pa[0].x, pa[0].y, pa[0].z, pa[0].w,
                            pa[1].x, pa[1].y, pa[1].z, pa[1].w};
        unsigned hi[4], lo[4];
#pragma unroll
        for (int q = 0; q < 4; ++q) {
            const float a = f[2 * q], b = f[2 * q + 1];
            const float ra = a - __half2float(__float2half(a));
            const float rb = b - __half2float(__float2half(b));
            hi[q] = pack2h(a, b);
            lo[q] = pack2h(ra, rb);
        }
        char* base = smem + s * H_STAGE;
        const unsigned off = (unsigned)(ar * STRD + ac0 * 2);
        *(uint4*)(base + off)             = make_uint4(hi[0], hi[1], hi[2], hi[3]);
        *(uint4*)(base + H_OFF_ALO + off) = make_uint4(lo[0], lo[1], lo[2], lo[3]);
    };
    const int br = tid >> 2;
    const int bc = tid & 3;
    auto cpB = [&](int s, int k0) {
        const unsigned d = sbase + s * H_STAGE + H_OFF_B + br * STRD + bc * 16;
        cpa16(d, Bp + (long long)br * lda + k0 + bc * 8);
        asm volatile("cp.async.commit_group;" ::: "memory");
    };

    ldA(0);
    cpB(0, 0);
    stA(0);
    asm volatile("cp.async.wait_group 0;" ::: "memory");
    __syncthreads();

    float acc[2][4][4];
#pragma unroll
    for (int i = 0; i < 2; ++i)
#pragma unroll
        for (int j = 0; j < 4; ++j)
#pragma unroll
            for (int e = 0; e < 4; ++e) acc[i][j][e] = 0.f;

    const int lrow = lane & 7, quad = lane >> 3;
    const unsigned aoff =
        (unsigned)((wm * 32 + lrow + (quad & 1) * 8) * STRD + ((quad >> 1) * 8) * 2);
    const unsigned boff =
        (unsigned)((wn * 32 + lrow + (quad >> 1) * 8) * STRD + ((quad & 1) * 8) * 2);

    const int nIter = kseg >> 5;
    for (int it = 0; it < nIter; ++it) {
        const int s = it & 1;
        const unsigned sb = sbase + s * H_STAGE;
        const bool more = (it + 1 < nIter);
        if (more) { ldA((it + 1) * BK); cpB(s ^ 1, (it + 1) * BK); }

#pragma unroll
        for (int k2 = 0; k2 < 2; ++k2) {
            const unsigned kb = (unsigned)(k2 * 32);
            unsigned a_hi[2][4], a_lo[2][4];
#pragma unroll
            for (int i = 0; i < 2; ++i) {
                ldsm4(a_hi[i], sb + aoff + i * 16 * STRD + kb);
                ldsm4(a_lo[i], sb + H_OFF_ALO + aoff + i * 16 * STRD + kb);
            }
#pragma unroll
            for (int p = 0; p < 2; ++p) {
                unsigned bfr[4];
                ldsm4(bfr, sb + H_OFF_B + boff + p * 16 * STRD + kb);
#pragma unroll
                for (int i = 0; i < 2; ++i) {
                    mma_h(acc[i][2 * p + 0], a_hi[i], bfr + 0);
                    mma_h(acc[i][2 * p + 1], a_hi[i], bfr + 2);
                    mma_h(acc[i][2 * p + 0], a_lo[i], bfr + 0);
                    mma_h(acc[i][2 * p + 1], a_lo[i], bfr + 2);
                }
            }
        }
        if (more) {
            stA(s ^ 1);
            asm volatile("cp.async.wait_group 0;" ::: "memory");
        }
        __syncthreads();
    }

    const int r4 = lane >> 2, c2 = (lane & 3) * 2;
#pragma unroll
    for (int i = 0; i < 2; ++i) {
        const long long rg0 = row0 + wm * 32 + i * 16 + r4;
#pragma unroll
        for (int j = 0; j < 4; ++j) {
            const int cg = n0 + wn * 32 + j * 8 + c2;
            float2 v0 = make_float2(acc[i][j][0], acc[i][j][1]);
            float2 v1 = make_float2(acc[i][j][2], acc[i][j][3]);
            const float bx = bias[cg], by = bias[cg + 1];
            if (EPI == 2) {
                v0.x = fmaxf(v0.x + bx, 0.f); v0.y = fmaxf(v0.y + by, 0.f);
                v1.x = fmaxf(v1.x + bx, 0.f); v1.y = fmaxf(v1.y + by, 0.f);
            } else {
                v0.x += bx; v0.y += by;
                v1.x += bx; v1.y += by;
            }
            *(float2*)(C + rg0 * ldC + cg)       = v0;
            *(float2*)(C + (rg0 + 8) * ldC + cg) = v1;
        }
    }
}

extern "C" void kernel_launch(void* const* d_in, const int* in_sizes, int n_in,
                              void* d_out, int out_size)
{
    (void)in_sizes; (void)n_in; (void)out_size;
    const float* x   = (const float*)d_in[0];
    const float* adj = (const float*)d_in[1];
    const float* eps = (const float*)d_in[2];
    const float* W1  = (const float*)d_in[3];
    const float* b1  = (const float*)d_in[4];
    const float* W2  = (const float*)d_in[5];
    const float* b2  = (const float*)d_in[6];
    float* out = (float*)d_out;

    float *h1, *part;
    __half *bxh, *w1h, *w2h;
    cudaGetSymbolAddress((void**)&h1,   g_h1);
    cudaGetSymbolAddress((void**)&part, g_part);
    cudaGetSymbolAddress((void**)&bxh,  g_Bx_h);
    cudaGetSymbolAddress((void**)&w1h,  g_W1_h);
    cudaGetSymbolAddress((void**)&w2h,  g_W2_h);

    cudaFuncSetAttribute(gemm_k1,    cudaFuncAttributeMaxDynamicSharedMemorySize, F_SMEM);
    cudaFuncSetAttribute(gemm_h2<2>, cudaFuncAttributeMaxDynamicSharedMemorySize, H_SMEM);
    cudaFuncSetAttribute(gemm_h2<3>, cudaFuncAttributeMaxDynamicSharedMemorySize, H_SMEM);

    const dim3 tb(32, 8);
    pack_x_h<<<dim3(128, 8, 8), tb>>>(x, bxh);
    pack_w_h<<<dim3(8, 16, 1),  tb>>>(W1, w1h, 256, 512);
    pack_w_h<<<dim3(16, 8, 1),  tb>>>(W2, w2h, 512, 256);

    // K1: part[sp][b] = adj[b][:, seg]@x[b][seg]   fp16 2-pass, BN=256
    gemm_k1<<<dim3(1, 32, 32), 512, F_SMEM>>>(
        adj, bxh, part,
        /*lda=*/4096, /*ldC=*/256, /*kseg=*/1024,
        4096LL * 4096, 256LL * 4096, 4096LL * 256);

    // K2: h1 = relu(((1+eps)x + sum part)@W1 + b1)
    gemm_h2<2><<<dim3(4, 256, 1), 512, H_SMEM>>>(
        x, w1h, h1, b1, part, eps,
        /*lda=*/256, /*ldC=*/512, /*kseg=*/256);

    // K3: out = h1@W2 + b2
    gemm_h2<3><<<dim3(2, 256, 1), 512, H_SMEM>>>(
        h1, w2h, out, b2, nullptr, nullptr,
        /*lda=*/512, /*ldC=*/256, /*kseg=*/512);
}